// round 2
// baseline (speedup 1.0000x reference)
#include <cuda_runtime.h>

// VDEncoderDecoder: stacked LSTM encoder (8->32->8->1 over T=48) +
// decoder (1->2->2->1 over 60 steps) + fused fc(60->32->12) via g = fc2_w @ fc1_w.
// One thread per batch element; all layers fused per timestep; weights in smem.
// Unit loops for H=32/H=8 layers are runtime loops (unroll 1) to bound register
// pressure; only c[]/hn[] (dynamically indexed, ~350B) live on the stack.

#define TPB 128
static constexpr int BATCH = 32768;
static constexpr int T = 48;

// shared-memory float offsets
static constexpr int OFF_W1IH = 0;       // 128x8   = 1024
static constexpr int OFF_W1HH = 1024;    // 128x32  = 4096
static constexpr int OFF_B1   = 5120;    // 128
static constexpr int OFF_W2IH = 5248;    // 32x32   = 1024
static constexpr int OFF_W2HH = 6272;    // 32x8    = 256
static constexpr int OFF_B2   = 6528;    // 32
static constexpr int OFF_W3IH = 6560;    // 4x8     = 32
static constexpr int OFF_W3HH = 6592;    // 4
static constexpr int OFF_B3   = 6596;    // 4
static constexpr int OFF_D1IH = 6600;    // 8
static constexpr int OFF_D1HH = 6608;    // 16
static constexpr int OFF_BD1  = 6624;    // 8
static constexpr int OFF_D2IH = 6632;    // 16
static constexpr int OFF_D2HH = 6648;    // 16
static constexpr int OFF_BD2  = 6664;    // 8
static constexpr int OFF_D3IH = 6672;    // 8
static constexpr int OFF_D3HH = 6680;    // 4
static constexpr int OFF_BD3  = 6684;    // 4
static constexpr int OFF_G    = 6688;    // 60x12 = 720  (g[t*12+j] = sum_k fc2w[j,k]*fc1w[k,t])
static constexpr int OFF_CB   = 7408;    // 12           (fc2b + fc2w @ fc1b)
static constexpr int SMEM_FLOATS = 7424;

__device__ __forceinline__ float sigf(float x) {
    return __fdividef(1.0f, 1.0f + __expf(-x));
}
__device__ __forceinline__ float tanhx(float x) {
    float e = __expf(2.0f * x);
    return 1.0f - __fdividef(2.0f, e + 1.0f);
}

// Large LSTM cell: runtime unit loop (unroll 1). h/x register arrays are only
// indexed statically (inner loops fully unrolled); c/hn indexed by runtime u
// (small stack arrays). Four independent accumulator chains per unit for ILP.
template<int H, int DIN>
__device__ __forceinline__ void lstm_big(
    const float* __restrict__ wih, const float* __restrict__ whh,
    const float* __restrict__ bias,
    const float (&xin)[DIN], float (&h)[H], float* __restrict__ c)
{
    float hn[H];
#pragma unroll 1
    for (int u = 0; u < H; ++u) {
        float a0 = bias[u];
        float a1 = bias[H + u];
        float a2 = bias[2 * H + u];
        float a3 = bias[3 * H + u];
        const float* w0 = wih + u * DIN;
        const float* w1 = wih + (H + u) * DIN;
        const float* w2 = wih + (2 * H + u) * DIN;
        const float* w3 = wih + (3 * H + u) * DIN;
#pragma unroll
        for (int d = 0; d < DIN; ++d) {
            float xv = xin[d];
            a0 = fmaf(xv, w0[d], a0);
            a1 = fmaf(xv, w1[d], a1);
            a2 = fmaf(xv, w2[d], a2);
            a3 = fmaf(xv, w3[d], a3);
        }
        const float* v0 = whh + u * H;
        const float* v1 = whh + (H + u) * H;
        const float* v2 = whh + (2 * H + u) * H;
        const float* v3 = whh + (3 * H + u) * H;
#pragma unroll
        for (int j = 0; j < H; ++j) {
            float hv = h[j];
            a0 = fmaf(hv, v0[j], a0);
            a1 = fmaf(hv, v1[j], a1);
            a2 = fmaf(hv, v2[j], a2);
            a3 = fmaf(hv, v3[j], a3);
        }
        float ig = sigf(a0);
        float fg = sigf(a1);
        float gg = tanhx(a2);
        float og = sigf(a3);
        float cn = fmaf(fg, c[u], ig * gg);
        c[u] = cn;
        hn[u] = og * tanhx(cn);
    }
#pragma unroll
    for (int u = 0; u < H; ++u) h[u] = hn[u];
}

// Small LSTM cell: fully unrolled, everything in registers.
template<int H, int DIN>
__device__ __forceinline__ void lstm_small(
    const float* __restrict__ wih, const float* __restrict__ whh,
    const float* __restrict__ bias,
    const float (&xin)[DIN], float (&h)[H], float (&c)[H])
{
    float hn[H];
#pragma unroll
    for (int u = 0; u < H; ++u) {
        float a0 = bias[u];
        float a1 = bias[H + u];
        float a2 = bias[2 * H + u];
        float a3 = bias[3 * H + u];
#pragma unroll
        for (int d = 0; d < DIN; ++d) {
            float xv = xin[d];
            a0 = fmaf(xv, wih[u * DIN + d], a0);
            a1 = fmaf(xv, wih[(H + u) * DIN + d], a1);
            a2 = fmaf(xv, wih[(2 * H + u) * DIN + d], a2);
            a3 = fmaf(xv, wih[(3 * H + u) * DIN + d], a3);
        }
#pragma unroll
        for (int j = 0; j < H; ++j) {
            float hv = h[j];
            a0 = fmaf(hv, whh[u * H + j], a0);
            a1 = fmaf(hv, whh[(H + u) * H + j], a1);
            a2 = fmaf(hv, whh[(2 * H + u) * H + j], a2);
            a3 = fmaf(hv, whh[(3 * H + u) * H + j], a3);
        }
        float ig = sigf(a0);
        float fg = sigf(a1);
        float gg = tanhx(a2);
        float og = sigf(a3);
        float cn = fmaf(fg, c[u], ig * gg);
        c[u] = cn;
        hn[u] = og * tanhx(cn);
    }
#pragma unroll
    for (int u = 0; u < H; ++u) h[u] = hn[u];
}

__global__ void __launch_bounds__(TPB)
vd_encdec_kernel(
    const float* __restrict__ x,
    const float* __restrict__ w1ih, const float* __restrict__ w1hh, const float* __restrict__ b1,
    const float* __restrict__ w2ih, const float* __restrict__ w2hh, const float* __restrict__ b2,
    const float* __restrict__ w3ih, const float* __restrict__ w3hh, const float* __restrict__ b3,
    const float* __restrict__ d1ih, const float* __restrict__ d1hh, const float* __restrict__ bd1,
    const float* __restrict__ d2ih, const float* __restrict__ d2hh, const float* __restrict__ bd2,
    const float* __restrict__ d3ih, const float* __restrict__ d3hh, const float* __restrict__ bd3,
    const float* __restrict__ fc1w, const float* __restrict__ fc1b,
    const float* __restrict__ fc2w, const float* __restrict__ fc2b,
    float* __restrict__ out)
{
    __shared__ __align__(16) float sw[SMEM_FLOATS];
    const int tid = threadIdx.x;

    for (int i = tid; i < 1024; i += TPB) sw[OFF_W1IH + i] = w1ih[i];
    for (int i = tid; i < 4096; i += TPB) sw[OFF_W1HH + i] = w1hh[i];
    for (int i = tid; i < 128;  i += TPB) sw[OFF_B1   + i] = b1[i];
    for (int i = tid; i < 1024; i += TPB) sw[OFF_W2IH + i] = w2ih[i];
    for (int i = tid; i < 256;  i += TPB) sw[OFF_W2HH + i] = w2hh[i];
    for (int i = tid; i < 32;   i += TPB) sw[OFF_B2   + i] = b2[i];
    for (int i = tid; i < 32;   i += TPB) sw[OFF_W3IH + i] = w3ih[i];
    if (tid < 4)  sw[OFF_W3HH + tid] = w3hh[tid];
    if (tid < 4)  sw[OFF_B3   + tid] = b3[tid];
    if (tid < 8)  sw[OFF_D1IH + tid] = d1ih[tid];
    if (tid < 16) sw[OFF_D1HH + tid] = d1hh[tid];
    if (tid < 8)  sw[OFF_BD1 + tid] = bd1[tid];
    if (tid < 16) sw[OFF_D2IH + tid] = d2ih[tid];
    if (tid < 16) sw[OFF_D2HH + tid] = d2hh[tid];
    if (tid < 8)  sw[OFF_BD2 + tid] = bd2[tid];
    if (tid < 8)  sw[OFF_D3IH + tid] = d3ih[tid];
    if (tid < 4)  sw[OFF_D3HH + tid] = d3hh[tid];
    if (tid < 4)  sw[OFF_BD3 + tid] = bd3[tid];

    // g[t*12+j] = sum_k fc2w[j*32+k] * fc1w[k*60+t]   (from global, L2-cached)
    for (int i = tid; i < 720; i += TPB) {
        int t = i / 12, j = i % 12;
        float a = 0.0f;
        for (int k = 0; k < 32; ++k)
            a = fmaf(fc2w[j * 32 + k], fc1w[k * 60 + t], a);
        sw[OFF_G + i] = a;
    }
    if (tid < 12) {
        float a = fc2b[tid];
        for (int k = 0; k < 32; ++k)
            a = fmaf(fc2w[tid * 32 + k], fc1b[k], a);
        sw[OFF_CB + tid] = a;
    }
    __syncthreads();

    const int b = blockIdx.x * TPB + tid;
    const float* xb = x + (size_t)b * (T * 8);

    float h1[32], c1[32];
    float h2[8], c2[8];
    float h3[1], c3[1];
    float hd1[2], cd1[2], hd2[2], cd2[2], hd3[1], cd3[1];
    float acc[12];
#pragma unroll
    for (int i = 0; i < 32; ++i) { h1[i] = 0.0f; c1[i] = 0.0f; }
#pragma unroll
    for (int i = 0; i < 8; ++i) { h2[i] = 0.0f; c2[i] = 0.0f; }
    h3[0] = 0.0f; c3[0] = 0.0f;
#pragma unroll
    for (int i = 0; i < 2; ++i) { hd1[i] = 0.0f; cd1[i] = 0.0f; hd2[i] = 0.0f; cd2[i] = 0.0f; }
    hd3[0] = 0.0f; cd3[0] = 0.0f;
#pragma unroll
    for (int i = 0; i < 12; ++i) acc[i] = 0.0f;

    // ---- fused steps t = 0..47: encoder + decoder + fc accumulation ----
#pragma unroll 1
    for (int t = 0; t < T; ++t) {
        float4 xa = *reinterpret_cast<const float4*>(xb + t * 8);
        float4 xc = *reinterpret_cast<const float4*>(xb + t * 8 + 4);
        float xr[8] = { xa.x, xa.y, xa.z, xa.w, xc.x, xc.y, xc.z, xc.w };

        lstm_big<32, 8>(sw + OFF_W1IH, sw + OFF_W1HH, sw + OFF_B1, xr, h1, c1);
        lstm_big<8, 32>(sw + OFF_W2IH, sw + OFF_W2HH, sw + OFF_B2, h1, h2, c2);
        lstm_small<1, 8>(sw + OFF_W3IH, sw + OFF_W3HH, sw + OFF_B3, h2, h3, c3);

        float dv[1] = { h3[0] };
        lstm_small<2, 1>(sw + OFF_D1IH, sw + OFF_D1HH, sw + OFF_BD1, dv, hd1, cd1);
        lstm_small<2, 2>(sw + OFF_D2IH, sw + OFF_D2HH, sw + OFF_BD2, hd1, hd2, cd2);
        lstm_small<1, 2>(sw + OFF_D3IH, sw + OFF_D3HH, sw + OFF_BD3, hd2, hd3, cd3);

        float y = hd3[0];
        const float* gr = sw + OFF_G + t * 12;
#pragma unroll
        for (int j = 0; j < 12; ++j) acc[j] = fmaf(y, gr[j], acc[j]);
    }

    // ---- aux steps t = 48..59: decoder input = x[b, t-12, 4] ----
#pragma unroll
    for (int t = T; t < 60; ++t) {
        float dv[1] = { xb[(t - 12) * 8 + 4] };
        lstm_small<2, 1>(sw + OFF_D1IH, sw + OFF_D1HH, sw + OFF_BD1, dv, hd1, cd1);
        lstm_small<2, 2>(sw + OFF_D2IH, sw + OFF_D2HH, sw + OFF_BD2, hd1, hd2, cd2);
        lstm_small<1, 2>(sw + OFF_D3IH, sw + OFF_D3HH, sw + OFF_BD3, hd2, hd3, cd3);

        float y = hd3[0];
        const float* gr = sw + OFF_G + t * 12;
#pragma unroll
        for (int j = 0; j < 12; ++j) acc[j] = fmaf(y, gr[j], acc[j]);
    }

    // ---- epilogue: out = acc + cbias ----
    float4 o0, o1, o2;
    o0.x = acc[0] + sw[OFF_CB + 0];  o0.y = acc[1] + sw[OFF_CB + 1];
    o0.z = acc[2] + sw[OFF_CB + 2];  o0.w = acc[3] + sw[OFF_CB + 3];
    o1.x = acc[4] + sw[OFF_CB + 4];  o1.y = acc[5] + sw[OFF_CB + 5];
    o1.z = acc[6] + sw[OFF_CB + 6];  o1.w = acc[7] + sw[OFF_CB + 7];
    o2.x = acc[8] + sw[OFF_CB + 8];  o2.y = acc[9] + sw[OFF_CB + 9];
    o2.z = acc[10] + sw[OFF_CB + 10]; o2.w = acc[11] + sw[OFF_CB + 11];
    float4* op = reinterpret_cast<float4*>(out + (size_t)b * 12);
    op[0] = o0; op[1] = o1; op[2] = o2;
}

extern "C" void kernel_launch(void* const* d_in, const int* in_sizes, int n_in,
                              void* d_out, int out_size) {
    (void)in_sizes; (void)n_in; (void)out_size;
    const float* x    = (const float*)d_in[0];
    const float* w1ih = (const float*)d_in[1];
    const float* w1hh = (const float*)d_in[2];
    const float* b1   = (const float*)d_in[3];
    const float* w2ih = (const float*)d_in[4];
    const float* w2hh = (const float*)d_in[5];
    const float* b2   = (const float*)d_in[6];
    const float* w3ih = (const float*)d_in[7];
    const float* w3hh = (const float*)d_in[8];
    const float* b3   = (const float*)d_in[9];
    const float* d1ih = (const float*)d_in[10];
    const float* d1hh = (const float*)d_in[11];
    const float* bd1  = (const float*)d_in[12];
    const float* d2ih = (const float*)d_in[13];
    const float* d2hh = (const float*)d_in[14];
    const float* bd2  = (const float*)d_in[15];
    const float* d3ih = (const float*)d_in[16];
    const float* d3hh = (const float*)d_in[17];
    const float* bd3  = (const float*)d_in[18];
    const float* fc1w = (const float*)d_in[19];
    const float* fc1b = (const float*)d_in[20];
    const float* fc2w = (const float*)d_in[21];
    const float* fc2b = (const float*)d_in[22];
    float* out = (float*)d_out;

    dim3 grid(BATCH / TPB);
    dim3 block(TPB);
    vd_encdec_kernel<<<grid, block>>>(
        x, w1ih, w1hh, b1, w2ih, w2hh, b2, w3ih, w3hh, b3,
        d1ih, d1hh, bd1, d2ih, d2hh, bd2, d3ih, d3hh, bd3,
        fc1w, fc1b, fc2w, fc2b, out);
}

// round 3
// speedup vs baseline: 1.0295x; 1.0295x over previous
#include <cuda_runtime.h>

// VDEncoderDecoder: stacked LSTM encoder (8->32->8->1, T=48) + decoder
// (1->2->2->1, 60 steps) + fused fc via g = fc2_w @ fc1_w.
// One thread per batch element. Big layers (e1, e2) use fma.rn.f32x2 packed
// gate-pairs (i,f)/(g,o) with weights stored in smem as 64-bit pairs and
// loaded as ulonglong2 (LDS.128). Old hidden state kept packed in registers.

#define TPB 128
static constexpr int BATCH = 32768;
static constexpr int T = 48;

// packed (u64) smem offsets
static constexpr int P_E1IH = 0;     // (gp*32+u)*8+d        512
static constexpr int P_E1HH = 512;   // (gp*32+u)*32+j       2048
static constexpr int P_B1   = 2560;  // gp*32+u              64
static constexpr int P_E2IH = 2624;  // (gp*8+u)*32+d        512
static constexpr int P_E2HH = 3136;  // (gp*8+u)*8+j         128
static constexpr int P_B2   = 3264;  // gp*8+u               16
static constexpr int P_G    = 3280;  // t*6+j2               360
static constexpr int P_TOTAL = 3640;

// scalar (float) smem offsets
static constexpr int S_W3IH = 0;    // 32
static constexpr int S_W3HH = 32;   // 4
static constexpr int S_B3   = 36;   // 4
static constexpr int S_D1IH = 40;   // 8
static constexpr int S_D1HH = 48;   // 16
static constexpr int S_BD1  = 64;   // 8
static constexpr int S_D2IH = 72;   // 16
static constexpr int S_D2HH = 88;   // 16
static constexpr int S_BD2  = 104;  // 8
static constexpr int S_D3IH = 112;  // 8
static constexpr int S_D3HH = 120;  // 4
static constexpr int S_BD3  = 124;  // 4
static constexpr int S_CB   = 128;  // 12
static constexpr int S_TOTAL = 140;

typedef unsigned long long u64;

__device__ __forceinline__ u64 fma2(u64 a, u64 b, u64 c) {
    u64 d;
    asm("fma.rn.f32x2 %0, %1, %2, %3;" : "=l"(d) : "l"(a), "l"(b), "l"(c));
    return d;
}
__device__ __forceinline__ u64 pack2(float v) {
    u64 r;
    asm("mov.b64 %0, {%1, %1};" : "=l"(r) : "f"(v));
    return r;
}
__device__ __forceinline__ u64 pack2f(float lo, float hi) {
    u64 r;
    asm("mov.b64 %0, {%1, %2};" : "=l"(r) : "f"(lo), "f"(hi));
    return r;
}
__device__ __forceinline__ void unpack2(u64 v, float& lo, float& hi) {
    asm("mov.b64 {%0, %1}, %2;" : "=f"(lo), "=f"(hi) : "l"(v));
}

__device__ __forceinline__ float sigf(float x) {
    return __fdividef(1.0f, 1.0f + __expf(-x));
}
__device__ __forceinline__ float tanhx(float x) {
    float e = __expf(2.0f * x);
    return 1.0f - __fdividef(2.0f, e + 1.0f);
}

// Small scalar LSTM cell, fully unrolled (register-resident state).
template<int H, int DIN>
__device__ __forceinline__ void lstm_small(
    const float* __restrict__ wih, const float* __restrict__ whh,
    const float* __restrict__ bias,
    const float (&xin)[DIN], float (&h)[H], float (&c)[H])
{
    float hn[H];
#pragma unroll
    for (int u = 0; u < H; ++u) {
        float a0 = bias[u];
        float a1 = bias[H + u];
        float a2 = bias[2 * H + u];
        float a3 = bias[3 * H + u];
#pragma unroll
        for (int d = 0; d < DIN; ++d) {
            float xv = xin[d];
            a0 = fmaf(xv, wih[u * DIN + d], a0);
            a1 = fmaf(xv, wih[(H + u) * DIN + d], a1);
            a2 = fmaf(xv, wih[(2 * H + u) * DIN + d], a2);
            a3 = fmaf(xv, wih[(3 * H + u) * DIN + d], a3);
        }
#pragma unroll
        for (int j = 0; j < H; ++j) {
            float hv = h[j];
            a0 = fmaf(hv, whh[u * H + j], a0);
            a1 = fmaf(hv, whh[(H + u) * H + j], a1);
            a2 = fmaf(hv, whh[(2 * H + u) * H + j], a2);
            a3 = fmaf(hv, whh[(3 * H + u) * H + j], a3);
        }
        float ig = sigf(a0);
        float fg = sigf(a1);
        float gg = tanhx(a2);
        float og = sigf(a3);
        float cn = fmaf(fg, c[u], ig * gg);
        c[u] = cn;
        hn[u] = og * tanhx(cn);
    }
#pragma unroll
    for (int u = 0; u < H; ++u) h[u] = hn[u];
}

__global__ void __launch_bounds__(TPB)
vd_encdec_kernel(
    const float* __restrict__ x,
    const float* __restrict__ w1ih, const float* __restrict__ w1hh, const float* __restrict__ b1,
    const float* __restrict__ w2ih, const float* __restrict__ w2hh, const float* __restrict__ b2,
    const float* __restrict__ w3ih, const float* __restrict__ w3hh, const float* __restrict__ b3,
    const float* __restrict__ d1ih, const float* __restrict__ d1hh, const float* __restrict__ bd1,
    const float* __restrict__ d2ih, const float* __restrict__ d2hh, const float* __restrict__ bd2,
    const float* __restrict__ d3ih, const float* __restrict__ d3hh, const float* __restrict__ bd3,
    const float* __restrict__ fc1w, const float* __restrict__ fc1b,
    const float* __restrict__ fc2w, const float* __restrict__ fc2b,
    float* __restrict__ out)
{
    __shared__ __align__(16) u64 swp[P_TOTAL];
    __shared__ float sws[S_TOTAL];
    const int tid = threadIdx.x;

    // ---- stage packed weights ----
    // e1 ih pairs: gp0 -> rows (u, 32+u), gp1 -> rows (64+u, 96+u)
    for (int i = tid; i < 512; i += TPB) {
        int gp = i >> 8, rem = i & 255, u = rem >> 3, d = rem & 7;
        int r0 = gp * 64 + u, r1 = r0 + 32;
        swp[P_E1IH + i] = pack2f(w1ih[r0 * 8 + d], w1ih[r1 * 8 + d]);
    }
    for (int i = tid; i < 2048; i += TPB) {
        int gp = i >> 10, rem = i & 1023, u = rem >> 5, j = rem & 31;
        int r0 = gp * 64 + u, r1 = r0 + 32;
        swp[P_E1HH + i] = pack2f(w1hh[r0 * 32 + j], w1hh[r1 * 32 + j]);
    }
    for (int i = tid; i < 64; i += TPB) {
        int gp = i >> 5, u = i & 31;
        swp[P_B1 + i] = pack2f(b1[gp * 64 + u], b1[gp * 64 + 32 + u]);
    }
    // e2 (H=8): gp0 -> rows (u, 8+u), gp1 -> rows (16+u, 24+u)
    for (int i = tid; i < 512; i += TPB) {
        int gp = i >> 8, rem = i & 255, u = rem >> 5, d = rem & 31;
        int r0 = gp * 16 + u, r1 = r0 + 8;
        swp[P_E2IH + i] = pack2f(w2ih[r0 * 32 + d], w2ih[r1 * 32 + d]);
    }
    for (int i = tid; i < 128; i += TPB) {
        int gp = i >> 6, rem = i & 63, u = rem >> 3, j = rem & 7;
        int r0 = gp * 16 + u, r1 = r0 + 8;
        swp[P_E2HH + i] = pack2f(w2hh[r0 * 8 + j], w2hh[r1 * 8 + j]);
    }
    for (int i = tid; i < 16; i += TPB) {
        int gp = i >> 3, u = i & 7;
        swp[P_B2 + i] = pack2f(b2[gp * 16 + u], b2[gp * 16 + 8 + u]);
    }
    // fused fc: g[t][j] = sum_k fc2w[j,k] * fc1w[k,t], packed over j pairs
    for (int i = tid; i < 360; i += TPB) {
        int t = i / 6, j2 = i % 6;
        float g0 = 0.0f, g1 = 0.0f;
        for (int k = 0; k < 32; ++k) {
            float f1 = fc1w[k * 60 + t];
            g0 = fmaf(fc2w[(2 * j2) * 32 + k], f1, g0);
            g1 = fmaf(fc2w[(2 * j2 + 1) * 32 + k], f1, g1);
        }
        swp[P_G + i] = pack2f(g0, g1);
    }
    // scalar small-layer weights
    for (int i = tid; i < 32; i += TPB) sws[S_W3IH + i] = w3ih[i];
    if (tid < 4)  sws[S_W3HH + tid] = w3hh[tid];
    if (tid < 4)  sws[S_B3 + tid] = b3[tid];
    if (tid < 8)  sws[S_D1IH + tid] = d1ih[tid];
    if (tid < 16) sws[S_D1HH + tid] = d1hh[tid];
    if (tid < 8)  sws[S_BD1 + tid] = bd1[tid];
    if (tid < 16) sws[S_D2IH + tid] = d2ih[tid];
    if (tid < 16) sws[S_D2HH + tid] = d2hh[tid];
    if (tid < 8)  sws[S_BD2 + tid] = bd2[tid];
    if (tid < 8)  sws[S_D3IH + tid] = d3ih[tid];
    if (tid < 4)  sws[S_D3HH + tid] = d3hh[tid];
    if (tid < 4)  sws[S_BD3 + tid] = bd3[tid];
    if (tid < 12) {
        float a = fc2b[tid];
        for (int k = 0; k < 32; ++k)
            a = fmaf(fc2w[tid * 32 + k], fc1b[k], a);
        sws[S_CB + tid] = a;
    }
    __syncthreads();

    const int b = blockIdx.x * TPB + tid;
    const float* xb = x + (size_t)b * (T * 8);

    // packed old-h (registers, statically indexed only)
    u64 hp1[32], hp2[8];
    // runtime-indexed state (local mem, coalesced)
    float c1[32], hn1[32];
    float c2[8], hn2[8];
    float h3[1], c3[1];
    float hd1[2], cd1[2], hd2[2], cd2[2], hd3[1], cd3[1];
    u64 acc6[6];

#pragma unroll
    for (int i = 0; i < 32; ++i) { hp1[i] = 0ULL; c1[i] = 0.0f; }
#pragma unroll
    for (int i = 0; i < 8; ++i) { hp2[i] = 0ULL; c2[i] = 0.0f; hn2[i] = 0.0f; }
    h3[0] = 0.0f; c3[0] = 0.0f;
#pragma unroll
    for (int i = 0; i < 2; ++i) { hd1[i] = 0.0f; cd1[i] = 0.0f; hd2[i] = 0.0f; cd2[i] = 0.0f; }
    hd3[0] = 0.0f; cd3[0] = 0.0f;
#pragma unroll
    for (int i = 0; i < 6; ++i) acc6[i] = 0ULL;

    // ---- fused steps t = 0..47 ----
#pragma unroll 1
    for (int t = 0; t < T; ++t) {
        float4 xa = *reinterpret_cast<const float4*>(xb + t * 8);
        float4 xc = *reinterpret_cast<const float4*>(xb + t * 8 + 4);
        u64 xp[8];
        xp[0] = pack2(xa.x); xp[1] = pack2(xa.y); xp[2] = pack2(xa.z); xp[3] = pack2(xa.w);
        xp[4] = pack2(xc.x); xp[5] = pack2(xc.y); xp[6] = pack2(xc.z); xp[7] = pack2(xc.w);

        // ---- e1: H=32, DIN=8 (packed) ----
#pragma unroll 1
        for (int u = 0; u < 32; ++u) {
            u64 aif = swp[P_B1 + u];
            u64 ago = swp[P_B1 + 32 + u];
            const ulonglong2* wif = reinterpret_cast<const ulonglong2*>(swp + P_E1IH + u * 8);
            const ulonglong2* wgo = reinterpret_cast<const ulonglong2*>(swp + P_E1IH + (32 + u) * 8);
#pragma unroll
            for (int dd = 0; dd < 4; ++dd) {
                ulonglong2 qa = wif[dd];
                ulonglong2 qb = wgo[dd];
                aif = fma2(qa.x, xp[2 * dd], aif);
                ago = fma2(qb.x, xp[2 * dd], ago);
                aif = fma2(qa.y, xp[2 * dd + 1], aif);
                ago = fma2(qb.y, xp[2 * dd + 1], ago);
            }
            const ulonglong2* vif = reinterpret_cast<const ulonglong2*>(swp + P_E1HH + u * 32);
            const ulonglong2* vgo = reinterpret_cast<const ulonglong2*>(swp + P_E1HH + (32 + u) * 32);
#pragma unroll
            for (int jj = 0; jj < 16; ++jj) {
                ulonglong2 qa = vif[jj];
                ulonglong2 qb = vgo[jj];
                aif = fma2(qa.x, hp1[2 * jj], aif);
                ago = fma2(qb.x, hp1[2 * jj], ago);
                aif = fma2(qa.y, hp1[2 * jj + 1], aif);
                ago = fma2(qb.y, hp1[2 * jj + 1], ago);
            }
            float ai, af, ag, ao;
            unpack2(aif, ai, af);
            unpack2(ago, ag, ao);
            float ig = sigf(ai), fg = sigf(af), gg = tanhx(ag), og = sigf(ao);
            float cn = fmaf(fg, c1[u], ig * gg);
            c1[u] = cn;
            hn1[u] = og * tanhx(cn);
        }
#pragma unroll
        for (int j = 0; j < 32; ++j) hp1[j] = pack2(hn1[j]);

        // ---- e2: H=8, DIN=32 (packed), input = h1 ----
#pragma unroll 1
        for (int u = 0; u < 8; ++u) {
            u64 aif = swp[P_B2 + u];
            u64 ago = swp[P_B2 + 8 + u];
            const ulonglong2* wif = reinterpret_cast<const ulonglong2*>(swp + P_E2IH + u * 32);
            const ulonglong2* wgo = reinterpret_cast<const ulonglong2*>(swp + P_E2IH + (8 + u) * 32);
#pragma unroll
            for (int dd = 0; dd < 16; ++dd) {
                ulonglong2 qa = wif[dd];
                ulonglong2 qb = wgo[dd];
                aif = fma2(qa.x, hp1[2 * dd], aif);
                ago = fma2(qb.x, hp1[2 * dd], ago);
                aif = fma2(qa.y, hp1[2 * dd + 1], aif);
                ago = fma2(qb.y, hp1[2 * dd + 1], ago);
            }
            const ulonglong2* vif = reinterpret_cast<const ulonglong2*>(swp + P_E2HH + u * 8);
            const ulonglong2* vgo = reinterpret_cast<const ulonglong2*>(swp + P_E2HH + (8 + u) * 8);
#pragma unroll
            for (int jj = 0; jj < 4; ++jj) {
                ulonglong2 qa = vif[jj];
                ulonglong2 qb = vgo[jj];
                aif = fma2(qa.x, hp2[2 * jj], aif);
                ago = fma2(qb.x, hp2[2 * jj], ago);
                aif = fma2(qa.y, hp2[2 * jj + 1], aif);
                ago = fma2(qb.y, hp2[2 * jj + 1], ago);
            }
            float ai, af, ag, ao;
            unpack2(aif, ai, af);
            unpack2(ago, ag, ao);
            float ig = sigf(ai), fg = sigf(af), gg = tanhx(ag), og = sigf(ao);
            float cn = fmaf(fg, c2[u], ig * gg);
            c2[u] = cn;
            hn2[u] = og * tanhx(cn);
        }
#pragma unroll
        for (int j = 0; j < 8; ++j) hp2[j] = pack2(hn2[j]);

        // ---- e3 + decoder (scalar, tiny) ----
        float x3[8];
#pragma unroll
        for (int j = 0; j < 8; ++j) x3[j] = hn2[j];
        lstm_small<1, 8>(sws + S_W3IH, sws + S_W3HH, sws + S_B3, x3, h3, c3);

        float dv[1] = { h3[0] };
        lstm_small<2, 1>(sws + S_D1IH, sws + S_D1HH, sws + S_BD1, dv, hd1, cd1);
        lstm_small<2, 2>(sws + S_D2IH, sws + S_D2HH, sws + S_BD2, hd1, hd2, cd2);
        lstm_small<1, 2>(sws + S_D3IH, sws + S_D3HH, sws + S_BD3, hd2, hd3, cd3);

        u64 yp = pack2(hd3[0]);
        const u64* gr = swp + P_G + t * 6;
#pragma unroll
        for (int j = 0; j < 6; ++j) acc6[j] = fma2(yp, gr[j], acc6[j]);
    }

    // ---- aux steps t = 48..59: decoder input = x[b, t-12, 4] ----
#pragma unroll 1
    for (int t = T; t < 60; ++t) {
        float dv[1] = { xb[(t - 12) * 8 + 4] };
        lstm_small<2, 1>(sws + S_D1IH, sws + S_D1HH, sws + S_BD1, dv, hd1, cd1);
        lstm_small<2, 2>(sws + S_D2IH, sws + S_D2HH, sws + S_BD2, hd1, hd2, cd2);
        lstm_small<1, 2>(sws + S_D3IH, sws + S_D3HH, sws + S_BD3, hd2, hd3, cd3);

        u64 yp = pack2(hd3[0]);
        const u64* gr = swp + P_G + t * 6;
#pragma unroll
        for (int j = 0; j < 6; ++j) acc6[j] = fma2(yp, gr[j], acc6[j]);
    }

    // ---- epilogue ----
    float r[12];
#pragma unroll
    for (int j = 0; j < 6; ++j) {
        float lo, hi;
        unpack2(acc6[j], lo, hi);
        r[2 * j] = lo + sws[S_CB + 2 * j];
        r[2 * j + 1] = hi + sws[S_CB + 2 * j + 1];
    }
    float4* op = reinterpret_cast<float4*>(out + (size_t)b * 12);
    op[0] = make_float4(r[0], r[1], r[2], r[3]);
    op[1] = make_float4(r[4], r[5], r[6], r[7]);
    op[2] = make_float4(r[8], r[9], r[10], r[11]);
}

extern "C" void kernel_launch(void* const* d_in, const int* in_sizes, int n_in,
                              void* d_out, int out_size) {
    (void)in_sizes; (void)n_in; (void)out_size;
    const float* x    = (const float*)d_in[0];
    const float* w1ih = (const float*)d_in[1];
    const float* w1hh = (const float*)d_in[2];
    const float* b1   = (const float*)d_in[3];
    const float* w2ih = (const float*)d_in[4];
    const float* w2hh = (const float*)d_in[5];
    const float* b2   = (const float*)d_in[6];
    const float* w3ih = (const float*)d_in[7];
    const float* w3hh = (const float*)d_in[8];
    const float* b3   = (const float*)d_in[9];
    const float* d1ih = (const float*)d_in[10];
    const float* d1hh = (const float*)d_in[11];
    const float* bd1  = (const float*)d_in[12];
    const float* d2ih = (const float*)d_in[13];
    const float* d2hh = (const float*)d_in[14];
    const float* bd2  = (const float*)d_in[15];
    const float* d3ih = (const float*)d_in[16];
    const float* d3hh = (const float*)d_in[17];
    const float* bd3  = (const float*)d_in[18];
    const float* fc1w = (const float*)d_in[19];
    const float* fc1b = (const float*)d_in[20];
    const float* fc2w = (const float*)d_in[21];
    const float* fc2b = (const float*)d_in[22];
    float* out = (float*)d_out;

    dim3 grid(BATCH / TPB);
    dim3 block(TPB);
    vd_encdec_kernel<<<grid, block>>>(
        x, w1ih, w1hh, b1, w2ih, w2hh, b2, w3ih, w3hh, b3,
        d1ih, d1hh, bd1, d2ih, d2hh, bd2, d3ih, d3hh, bd3,
        fc1w, fc1b, fc2w, fc2b, out);
}